// round 17
// baseline (speedup 1.0000x reference)
#include <cuda_runtime.h>
#include <cstdint>

#define Bdim 256
#define Udim 512
#define Ddim 512
#define N4U  2048
#define DLAG 16

typedef unsigned long long ull;

// ---------------- scratch ----------------
__device__ float g_pre  [Bdim * N4U];
__device__ float g_hw   [Bdim * Udim];
__device__ float g_red16[Bdim * 16 * Udim];
__device__ float g_g    [Bdim * Udim];
__device__ int   d_gemm_cnt;
__device__ int   d_red_cnt[Bdim];
__device__ int   d_flag[Bdim];

// ---------------- packed f32x2 helpers ----------------
__device__ __forceinline__ ull pk2(float x, float y) {
    ull r; asm("mov.b64 %0, {%1, %2};" : "=l"(r) : "f"(x), "f"(y)); return r;
}
__device__ __forceinline__ ull fma2(ull a, ull b, ull c) {
    ull d; asm("fma.rn.f32x2 %0, %1, %2, %3;" : "=l"(d) : "l"(a), "l"(b), "l"(c)); return d;
}
__device__ __forceinline__ float2 upk(ull v) {
    float2 r; asm("mov.b64 {%0, %1}, %2;" : "=f"(r.x), "=f"(r.y) : "l"(v)); return r;
}
__device__ __forceinline__ float hsig(float z) {
    return fminf(fmaxf(0.2f * z + 0.5f, 0.f), 1.f);
}

// ---------------- init: reset sync state each replay ----------------
__global__ void init_kernel() {
    int i = threadIdx.x;
    if (i == 0) d_gemm_cnt = 0;
    if (i < Bdim) { d_red_cnt[i] = 0; d_flag[i] = 0; }
}

// ---------------- GEMM tile ----------------
__device__ __forceinline__ void gemm32x64(
    const float* __restrict__ A1, const float* __restrict__ B1,
    const float* __restrict__ A2, const float* __restrict__ B2,
    const float* __restrict__ bias, float* __restrict__ C,
    int N, int m0, int n0, bool do_rec, bool add_bias, float* smem)
{
    const int K = 512;
    float (*As)[32] = (float(*)[32])smem;
    float (*Bs)[64] = (float(*)[64])(smem + 512);

    int tid = threadIdx.x;
    int tx  = tid & 15;
    int ty  = tid >> 4;

    ull acc[2][2];
    acc[0][0] = acc[0][1] = acc[1][0] = acc[1][1] = 0ull;

    int npass = do_rec ? 2 : 1;
    for (int pass = 0; pass < npass; ++pass) {
        const float* A = pass ? A2 : A1;
        const float* B = pass ? B2 : B1;
        for (int k0 = 0; k0 < K; k0 += 16) {
            #pragma unroll
            for (int t = 0; t < 2; ++t) {
                int i = tid + t * 256;
                As[i & 15][i >> 4] = A[(m0 + (i >> 4)) * K + k0 + (i & 15)];
            }
            #pragma unroll
            for (int t = 0; t < 4; ++t) {
                int i = tid + t * 256;
                Bs[i >> 6][i & 63] = B[(k0 + (i >> 6)) * N + n0 + (i & 63)];
            }
            __syncthreads();
            #pragma unroll
            for (int kk = 0; kk < 16; ++kk) {
                float2 av = *(const float2*)&As[kk][ty * 2];
                ulonglong2 bv = *(const ulonglong2*)&Bs[kk][tx * 4];
                ull a0 = pk2(av.x, av.x);
                ull a1 = pk2(av.y, av.y);
                acc[0][0] = fma2(a0, bv.x, acc[0][0]);
                acc[0][1] = fma2(a0, bv.y, acc[0][1]);
                acc[1][0] = fma2(a1, bv.x, acc[1][0]);
                acc[1][1] = fma2(a1, bv.y, acc[1][1]);
            }
            __syncthreads();
        }
    }

    int n = n0 + tx * 4;
    float b0 = 0.f, b1 = 0.f, b2 = 0.f, b3 = 0.f;
    if (add_bias) { b0 = bias[n]; b1 = bias[n+1]; b2 = bias[n+2]; b3 = bias[n+3]; }
    #pragma unroll
    for (int r = 0; r < 2; ++r) {
        int m = m0 + ty * 2 + r;
        float2 lo = upk(acc[r][0]);
        float2 hi = upk(acc[r][1]);
        float4 o = make_float4(lo.x + b0, lo.y + b1, hi.x + b2, hi.y + b3);
        *(float4*)&C[m * N + n] = o;
    }
}

// ---------------- reduce item: (b, 32-u chunk), plain loads ----------
__device__ __forceinline__ void reduce_item(
    const float* __restrict__ hebb, const float* __restrict__ h_tm1,
    int b, int chunk, float* smem)
{
    int tid = threadIdx.x;
    int v4  = tid & 127;
    int uh  = tid >> 7;

    float* fold = smem;
    ull*   hs2  = (ull*)(smem + 512);

    if (tid < 32) {
        float hv = h_tm1[(b << 9) + (chunk << 5) + tid];
        hs2[tid] = pk2(hv, hv);
    }
    __syncthreads();

    const float4* p = (const float4*)(hebb
        + ((size_t)b << 18)
        + ((size_t)(chunk * 32 + uh * 16) << 9)) + v4;
    const ull* hb = hs2 + uh * 16;

    ull a0x = 0, a0y = 0, a1x = 0, a1y = 0;
    ull a2x = 0, a2y = 0, a3x = 0, a3y = 0;
    #pragma unroll
    for (int k = 0; k < 4; ++k) {
        float4 l0 = p[(size_t)(k * 4 + 0) * 128];
        float4 l1 = p[(size_t)(k * 4 + 1) * 128];
        float4 l2 = p[(size_t)(k * 4 + 2) * 128];
        float4 l3 = p[(size_t)(k * 4 + 3) * 128];
        ull h0 = hb[k * 4 + 0], h1 = hb[k * 4 + 1];
        ull h2 = hb[k * 4 + 2], h3 = hb[k * 4 + 3];
        ulonglong2 v0 = *(ulonglong2*)&l0;
        ulonglong2 v1 = *(ulonglong2*)&l1;
        ulonglong2 v2 = *(ulonglong2*)&l2;
        ulonglong2 v3 = *(ulonglong2*)&l3;
        a0x = fma2(h0, v0.x, a0x);  a0y = fma2(h0, v0.y, a0y);
        a1x = fma2(h1, v1.x, a1x);  a1y = fma2(h1, v1.y, a1y);
        a2x = fma2(h2, v2.x, a2x);  a2y = fma2(h2, v2.y, a2y);
        a3x = fma2(h3, v3.x, a3x);  a3y = fma2(h3, v3.y, a3y);
    }
    float2 s0 = upk(a0x), s1 = upk(a1x), s2 = upk(a2x), s3 = upk(a3x);
    float2 t0 = upk(a0y), t1 = upk(a1y), t2 = upk(a2y), t3 = upk(a3y);
    float4 acc = make_float4((s0.x + s1.x) + (s2.x + s3.x),
                             (s0.y + s1.y) + (s2.y + s3.y),
                             (t0.x + t1.x) + (t2.x + t3.x),
                             (t0.y + t1.y) + (t2.y + t3.y));

    __syncthreads();
    if (uh == 1) ((float4*)fold)[v4] = acc;
    __syncthreads();
    if (uh == 0) {
        float4 o = ((float4*)fold)[v4];
        acc.x += o.x; acc.y += o.y; acc.z += o.z; acc.w += o.w;
        ((float4*)(g_red16 + (size_t)(b * 16 + chunk) * Udim))[v4] = acc;
    }
    __syncthreads();
    if (tid == 0) { __threadfence(); atomicAdd(&d_red_cnt[b], 1); }
}

// ---------------- combine item ----------------
__device__ __forceinline__ void combine_item(
    const float* __restrict__ c_tm1, const float* __restrict__ alpha,
    const float* __restrict__ h2mod, const float* __restrict__ fanout,
    float* __restrict__ out, int b, float* smem)
{
    int tid = threadIdx.x;
    if (tid == 0) {
        while (*(volatile int*)&d_gemm_cnt < 320) __nanosleep(32);
        while (*(volatile int*)&d_red_cnt[b] < 16) __nanosleep(32);
    }
    __syncthreads();
    __threadfence();

    float hva[2], itca[2];
    #pragma unroll
    for (int half = 0; half < 2; ++half) {
        int v = tid + half * 256;
        const float* rr = g_red16 + (size_t)b * 16 * Udim + v;
        float p0 = 0.f, p1 = 0.f, p2 = 0.f, p3 = 0.f;
        #pragma unroll
        for (int j = 0; j < 16; j += 4) {
            p0 += rr[(j + 0) * Udim];
            p1 += rr[(j + 1) * Udim];
            p2 += rr[(j + 2) * Udim];
            p3 += rr[(j + 3) * Udim];
        }
        float red = (p0 + p1) + (p2 + p3);

        float xi = g_pre[b * N4U + v];
        float xf = g_pre[b * N4U + Udim + v];
        float xc = g_pre[b * N4U + 2 * Udim + v];
        float xo = g_pre[b * N4U + 3 * Udim + v];

        float gi = hsig(xi), gf = hsig(xf), go = hsig(xo);
        float itc = tanhf(xc + g_hw[b * Udim + v] + alpha[v] * red);
        float c = gf * c_tm1[b * Udim + v] + gi * itc;
        float h = go * tanhf(c);

        out[b * Udim + v] = h;
        out[Bdim * Udim + b * Udim + v] = c;
        hva[half] = h * h2mod[v];
        itca[half] = itc;
    }

    float s = hva[0] + hva[1];
    #pragma unroll
    for (int o = 16; o > 0; o >>= 1) s += __shfl_down_sync(0xffffffffu, s, o);
    float* ws = smem;
    if ((tid & 31) == 0) ws[tid >> 5] = s;
    __syncthreads();
    if (tid == 0) {
        float tot = ((ws[0] + ws[1]) + (ws[2] + ws[3]))
                  + ((ws[4] + ws[5]) + (ws[6] + ws[7]));
        ws[8] = tanhf(tot);
    }
    __syncthreads();
    float eta = ws[8];

    g_g[b * Udim + tid]       = eta * fanout[tid]       * itca[0];
    g_g[b * Udim + tid + 256] = eta * fanout[tid + 256] * itca[1];

    __syncthreads();
    if (tid == 0) { __threadfence(); *(volatile int*)&d_flag[b] = 1; }
}

// ---------------- update item: (b, j): 1024 consecutive f4 ----------
__device__ __forceinline__ void update_item(
    const float* __restrict__ hebb, const float* __restrict__ h_tm1,
    float* __restrict__ outh, int b, int j)
{
    int tid = threadIdx.x;
    if (tid == 0) {
        while (*(volatile int*)&d_flag[b] == 0) __nanosleep(32);
    }
    __syncthreads();
    __threadfence();

    int base = (b << 16) + j * 1024 + tid;
    #pragma unroll
    for (int k = 0; k < 4; ++k) {
        int idx = base + k * 256;
        int row = idx >> 7;
        int v4  = idx & 127;

        float hu = h_tm1[row];
        float4 hv = __ldcs(((const float4*)hebb) + idx);   // L2-warm (16-b lag)
        float4 gg = ((const float4*)(g_g + (b << 9)))[v4];

        float4 r;
        r.x = fminf(fmaxf(hv.x + hu * gg.x, -2.f), 2.f);
        r.y = fminf(fmaxf(hv.y + hu * gg.y, -2.f), 2.f);
        r.z = fminf(fmaxf(hv.z + hu * gg.z, -2.f), 2.f);
        r.w = fminf(fmaxf(hv.w + hu * gg.w, -2.f), 2.f);
        __stcs(((float4*)outh) + idx, r);
    }
}

// =======================================================================
// Mega kernel — INTERLEAVED bid layout:
//  [0,320)        GEMM
//  [320,576)      reduce b=0..15
//  [576,20016)    groups of 81 for b=16..255:
//                   k<16: reduce(b,k); k==16: combine(b-16); else update(b-16,k-17)
//  [20016,21056)  tail: groups of 65 for b=240..255: combine(b) + 64 updates
// =======================================================================
__global__ void __launch_bounds__(256) mega_kernel(
    const float* __restrict__ x,     const float* __restrict__ kernel,
    const float* __restrict__ h_tm1, const float* __restrict__ rec,
    const float* __restrict__ bias,  const float* __restrict__ w,
    const float* __restrict__ hebb,  const float* __restrict__ c_tm1,
    const float* __restrict__ alpha, const float* __restrict__ h2mod,
    const float* __restrict__ fanout, float* __restrict__ out)
{
    __shared__ __align__(16) float smem[1536];
    int bid = blockIdx.x;
    int tid = threadIdx.x;
    float* outh = out + 2 * Bdim * Udim;

    if (bid < 320) {
        if (bid < 256) {
            int n0 = (bid & 31) * 64;
            int m0 = (bid >> 5) * 32;
            bool do_rec = !(n0 >= 2 * Udim && n0 < 3 * Udim);  // c-slice: no rec
            gemm32x64(x, kernel, h_tm1, rec, bias, g_pre, N4U, m0, n0, do_rec, true, smem);
        } else {
            int t  = bid - 256;
            int n0 = (t & 7) * 64;
            int m0 = (t >> 3) * 32;
            gemm32x64(h_tm1, w, nullptr, nullptr, nullptr, g_hw, Udim, m0, n0, false, false, smem);
        }
        __syncthreads();
        if (tid == 0) { __threadfence(); atomicAdd(&d_gemm_cnt, 1); }
    } else if (bid < 576) {
        int t = bid - 320;                       // b = 0..15
        reduce_item(hebb, h_tm1, t >> 4, t & 15, smem);
    } else if (bid < 20016) {
        int m = bid - 576;
        int g = m / 81;
        int k = m % 81;
        int b = DLAG + g;                        // 16..255
        if (k < 16)       reduce_item(hebb, h_tm1, b, k, smem);
        else if (k == 16) combine_item(c_tm1, alpha, h2mod, fanout, out, b - DLAG, smem);
        else              update_item(hebb, h_tm1, outh, b - DLAG, k - 17);
    } else {
        int m = bid - 20016;
        int g = m / 65;
        int k = m % 65;
        int b = (Bdim - DLAG) + g;               // 240..255
        if (k == 0) combine_item(c_tm1, alpha, h2mod, fanout, out, b, smem);
        else        update_item(hebb, h_tm1, outh, b, k - 1);
    }
}

// ---------------- launch ----------------
extern "C" void kernel_launch(void* const* d_in, const int* in_sizes, int n_in,
                              void* d_out, int out_size)
{
    const float* x      = (const float*)d_in[0];
    const float* h_tm1  = (const float*)d_in[1];
    const float* c_tm1  = (const float*)d_in[2];
    const float* hebb   = (const float*)d_in[3];
    const float* kernel = (const float*)d_in[4];
    const float* rec    = (const float*)d_in[5];
    const float* bias   = (const float*)d_in[6];
    const float* w      = (const float*)d_in[7];
    const float* alpha  = (const float*)d_in[8];
    const float* h2mod  = (const float*)d_in[9];
    const float* fanout = (const float*)d_in[10];
    float* out = (float*)d_out;

    init_kernel<<<1, 512>>>();
    mega_kernel<<<21056, 256>>>(x, kernel, h_tm1, rec, bias, w,
                                hebb, c_tm1, alpha, h2mod, fanout, out);
}